// round 3
// baseline (speedup 1.0000x reference)
#include <cuda_runtime.h>
#include <cuda_bf16.h>
#include <math.h>

// Problem constants (fixed by the dataset)
#define NMAX 50000
#define MMAX 800000
#define DEMB 256      // D = H*DK = H*DV = 256
#define HEADS 8
#define DHEAD 32

// ---------------------------------------------------------------------------
// Scratch (device globals: allocation-free per harness rules)
// ---------------------------------------------------------------------------
__device__ float g_K  [(size_t)NMAX * DEMB];
__device__ float g_Q  [(size_t)NMAX * DEMB];
__device__ float g_V  [(size_t)NMAX * DEMB];
__device__ float g_att[(size_t)MMAX * HEADS];   // qk logits, then att in-place
__device__ float g_sums[(size_t)NMAX * HEADS];  // segment softmax denominators
__device__ float g_agg[(size_t)NMAX * DEMB];    // scatter-add accumulator
__device__ float g_h1 [(size_t)NMAX * DEMB];    // after Wagg
__device__ float g_bmax[1024];                  // per-block maxima
__device__ float g_scale[1];                    // 3 / max(qk)

// ---------------------------------------------------------------------------
// GEMM: C[n,j] = epi( sum_d actIn(A[n,d]) * W[d*256+j] + bias[j] )
// BM=BN=64, BK=16, 256 threads, 4x4 microtile per thread.
// ---------------------------------------------------------------------------
template <bool RELU_IN, bool RELU_OUT, bool RESID>
__global__ __launch_bounds__(256)
void gemm256_kernel(const float* __restrict__ A, const float* __restrict__ W,
                    const float* __restrict__ bias, const float* __restrict__ resid,
                    float* __restrict__ C, int Nr)
{
    __shared__ float As[16][64];   // [k][m]
    __shared__ float Bs[16][64];   // [k][n]

    const int tid  = threadIdx.x;
    const int brow = blockIdx.y * 64;
    const int bcol = blockIdx.x * 64;
    const int tx = tid & 15;       // 16 col-threads
    const int ty = tid >> 4;       // 16 row-threads

    float acc[4][4] = {};

    // A loader: thread -> (row = tid/4, k4 = (tid&3)*4)
    const int arow = tid >> 2;
    const int ak   = (tid & 3) * 4;
    const int grow = brow + arow;
    const bool avalid = (grow < Nr);
    const float4* __restrict__ Arow4 =
        (const float4*)(A + (size_t)grow * DEMB);

    // W loader: thread -> (k = tid/16, j4 = (tid&15)*4)
    const int wk = tid >> 4;
    const int wj = (tid & 15) * 4;

    for (int k0 = 0; k0 < DEMB; k0 += 16) {
        float4 av = make_float4(0.f, 0.f, 0.f, 0.f);
        if (avalid) av = Arow4[(k0 + ak) >> 2];
        if (RELU_IN) {
            av.x = fmaxf(av.x, 0.f); av.y = fmaxf(av.y, 0.f);
            av.z = fmaxf(av.z, 0.f); av.w = fmaxf(av.w, 0.f);
        }
        As[ak + 0][arow] = av.x;
        As[ak + 1][arow] = av.y;
        As[ak + 2][arow] = av.z;
        As[ak + 3][arow] = av.w;

        float4 wv = *(const float4*)(W + (size_t)(k0 + wk) * DEMB + bcol + wj);
        *(float4*)&Bs[wk][wj] = wv;

        __syncthreads();

        #pragma unroll
        for (int k = 0; k < 16; k++) {
            float4 a4 = *(const float4*)&As[k][ty * 4];
            float4 b4 = *(const float4*)&Bs[k][tx * 4];
            acc[0][0] += a4.x * b4.x; acc[0][1] += a4.x * b4.y;
            acc[0][2] += a4.x * b4.z; acc[0][3] += a4.x * b4.w;
            acc[1][0] += a4.y * b4.x; acc[1][1] += a4.y * b4.y;
            acc[1][2] += a4.y * b4.z; acc[1][3] += a4.y * b4.w;
            acc[2][0] += a4.z * b4.x; acc[2][1] += a4.z * b4.y;
            acc[2][2] += a4.z * b4.z; acc[2][3] += a4.z * b4.w;
            acc[3][0] += a4.w * b4.x; acc[3][1] += a4.w * b4.y;
            acc[3][2] += a4.w * b4.z; acc[3][3] += a4.w * b4.w;
        }
        __syncthreads();
    }

    const float4 bi = *(const float4*)(bias + bcol + tx * 4);
    #pragma unroll
    for (int i = 0; i < 4; i++) {
        const int gr = brow + ty * 4 + i;
        if (gr >= Nr) break;
        float4 o;
        o.x = acc[i][0] + bi.x;
        o.y = acc[i][1] + bi.y;
        o.z = acc[i][2] + bi.z;
        o.w = acc[i][3] + bi.w;
        if (RELU_OUT) {
            o.x = fmaxf(o.x, 0.f); o.y = fmaxf(o.y, 0.f);
            o.z = fmaxf(o.z, 0.f); o.w = fmaxf(o.w, 0.f);
        }
        if (RESID) {
            float4 rr = *(const float4*)(resid + (size_t)gr * DEMB + bcol + tx * 4);
            o.x += rr.x; o.y += rr.y; o.z += rr.z; o.w += rr.w;
        }
        *(float4*)(C + (size_t)gr * DEMB + bcol + tx * 4) = o;
    }
}

// ---------------------------------------------------------------------------
// Edge QK dots (one warp per edge) + per-block max
// ---------------------------------------------------------------------------
__global__ __launch_bounds__(256)
void edge_qk_kernel(const int* __restrict__ recv, const int* __restrict__ send,
                    const float* __restrict__ Q, const float* __restrict__ K,
                    float* __restrict__ qk, float* __restrict__ bmax, int M)
{
    const int lane   = threadIdx.x & 31;
    const int warp   = (blockIdx.x * blockDim.x + threadIdx.x) >> 5;
    const int nwarps = (gridDim.x * blockDim.x) >> 5;

    float lmax = -3.402823e38f;
    for (int e = warp; e < M; e += nwarps) {
        const int r = recv[e];
        const int s = send[e];
        const float* __restrict__ q = Q + (size_t)r * DEMB;
        const float* __restrict__ k = K + (size_t)s * DEMB;
        float res[HEADS];
        #pragma unroll
        for (int h = 0; h < HEADS; h++) {
            float p = q[h * DHEAD + lane] * k[h * DHEAD + lane];
            #pragma unroll
            for (int off = 16; off; off >>= 1)
                p += __shfl_xor_sync(0xffffffffu, p, off);
            res[h] = p;
            lmax = fmaxf(lmax, p);
        }
        if (lane == 0) {
            #pragma unroll
            for (int h = 0; h < HEADS; h++)
                qk[(size_t)e * HEADS + h] = res[h];
        }
    }

    __shared__ float sm[256];
    sm[threadIdx.x] = lmax;
    __syncthreads();
    for (int s2 = 128; s2; s2 >>= 1) {
        if (threadIdx.x < s2)
            sm[threadIdx.x] = fmaxf(sm[threadIdx.x], sm[threadIdx.x + s2]);
        __syncthreads();
    }
    if (threadIdx.x == 0) bmax[blockIdx.x] = sm[0];
}

__global__ __launch_bounds__(1024)
void max_reduce_kernel(const float* __restrict__ bmax, int n, float* __restrict__ scale)
{
    __shared__ float sm[1024];
    float v = -3.402823e38f;
    for (int i = threadIdx.x; i < n; i += blockDim.x) v = fmaxf(v, bmax[i]);
    sm[threadIdx.x] = v;
    __syncthreads();
    for (int s = 512; s; s >>= 1) {
        if (threadIdx.x < s) sm[threadIdx.x] = fmaxf(sm[threadIdx.x], sm[threadIdx.x + s]);
        __syncthreads();
    }
    if (threadIdx.x == 0) scale[0] = 3.0f / sm[0];
}

// ---------------------------------------------------------------------------
// att = exp(qk * scale); segment-sum into sums[recv]
// ---------------------------------------------------------------------------
__global__ __launch_bounds__(256)
void edge_att_kernel(const int* __restrict__ recv, float* __restrict__ att,
                     const float* __restrict__ scale, float* __restrict__ sums, int MH)
{
    const float sc = scale[0];
    for (int i = blockIdx.x * blockDim.x + threadIdx.x; i < MH;
         i += gridDim.x * blockDim.x) {
        const int e = i >> 3;
        const int h = i & 7;
        const float a = expf(att[i] * sc);
        att[i] = a;
        atomicAdd(&sums[(size_t)recv[e] * HEADS + h], a);
    }
}

// ---------------------------------------------------------------------------
// Weighted scatter of V[send] into agg[recv] (one warp per edge)
// ---------------------------------------------------------------------------
__global__ __launch_bounds__(256)
void edge_scatter_kernel(const int* __restrict__ recv, const int* __restrict__ send,
                         const float* __restrict__ att, const float* __restrict__ sums,
                         const float* __restrict__ V, float* __restrict__ agg, int M)
{
    const float inv_sqrt_dk = 0.17677669529663687f;  // 1/sqrt(32)
    const int lane   = threadIdx.x & 31;
    const int warp   = (blockIdx.x * blockDim.x + threadIdx.x) >> 5;
    const int nwarps = (gridDim.x * blockDim.x) >> 5;

    for (int e = warp; e < M; e += nwarps) {
        const int r = recv[e];
        const int s = send[e];
        float w[HEADS];
        #pragma unroll
        for (int h = 0; h < HEADS; h++) {
            w[h] = att[(size_t)e * HEADS + h] /
                   sums[(size_t)r * HEADS + h] * inv_sqrt_dk;
        }
        const float* __restrict__ v = V + (size_t)s * DEMB;
        float* __restrict__ o = agg + (size_t)r * DEMB;
        #pragma unroll
        for (int h = 0; h < HEADS; h++)
            atomicAdd(&o[h * DHEAD + lane], w[h] * v[h * DHEAD + lane]);
    }
}

// ---------------------------------------------------------------------------
// Launch
// ---------------------------------------------------------------------------
extern "C" void kernel_launch(void* const* d_in, const int* in_sizes, int n_in,
                              void* d_out, int out_size)
{
    const float* x    = (const float*)d_in[0];
    const int*   ei   = (const int*)  d_in[1];
    const float* Wk   = (const float*)d_in[2];
    const float* bk   = (const float*)d_in[3];
    const float* Wq   = (const float*)d_in[4];
    const float* bq   = (const float*)d_in[5];
    const float* Wv   = (const float*)d_in[6];
    const float* bv   = (const float*)d_in[7];
    const float* Wagg = (const float*)d_in[8];
    const float* bagg = (const float*)d_in[9];
    const float* Wff  = (const float*)d_in[10];
    const float* bff  = (const float*)d_in[11];

    const int Nn = in_sizes[0] / DEMB;   // 50000
    const int M  = in_sizes[1] / 2;      // 800000
    const int* recv = ei;
    const int* send = ei + M;

    float *gK, *gQ, *gV, *gatt, *gsums, *gagg, *gh1, *gbmax, *gscale;
    cudaGetSymbolAddress((void**)&gK,    g_K);
    cudaGetSymbolAddress((void**)&gQ,    g_Q);
    cudaGetSymbolAddress((void**)&gV,    g_V);
    cudaGetSymbolAddress((void**)&gatt,  g_att);
    cudaGetSymbolAddress((void**)&gsums, g_sums);
    cudaGetSymbolAddress((void**)&gagg,  g_agg);
    cudaGetSymbolAddress((void**)&gh1,   g_h1);
    cudaGetSymbolAddress((void**)&gbmax, g_bmax);
    cudaGetSymbolAddress((void**)&gscale, g_scale);

    // Reset accumulators every launch (graph replays must be deterministic).
    cudaMemsetAsync(gsums, 0, (size_t)Nn * HEADS * sizeof(float), 0);
    cudaMemsetAsync(gagg,  0, (size_t)Nn * DEMB  * sizeof(float), 0);

    const dim3 gg(DEMB / 64, (Nn + 63) / 64);   // (4, 782)

    // 1) Projections K, Q, V
    gemm256_kernel<false, false, false><<<gg, 256>>>(x, Wk, bk, nullptr, gK, Nn);
    gemm256_kernel<false, false, false><<<gg, 256>>>(x, Wq, bq, nullptr, gQ, Nn);
    gemm256_kernel<false, false, false><<<gg, 256>>>(x, Wv, bv, nullptr, gV, Nn);

    // 2) Edge logits + global max
    edge_qk_kernel<<<1024, 256>>>(recv, send, gQ, gK, gatt, gbmax, M);
    max_reduce_kernel<<<1, 1024>>>(gbmax, 1024, gscale);

    // 3) exp + segment sums
    edge_att_kernel<<<2048, 256>>>(recv, gatt, gscale, gsums, M * HEADS);

    // 4) Weighted scatter into agg
    edge_scatter_kernel<<<2048, 256>>>(recv, send, gatt, gsums, gV, gagg, M);

    // 5) relu(agg) @ Wagg + bagg, relu
    gemm256_kernel<true, true, false><<<gg, 256>>>(gagg, Wagg, bagg, nullptr, gh1, Nn);

    // 6) h1 @ Wff + bff, relu, + x residual -> d_out
    gemm256_kernel<false, true, true><<<gg, 256>>>(gh1, Wff, bff, x, (float*)d_out, Nn);
}

// round 4
// speedup vs baseline: 2.1083x; 2.1083x over previous
#include <cuda_runtime.h>
#include <cuda_bf16.h>
#include <math.h>
#include <stdint.h>

// Problem constants (fixed by the dataset)
#define NMAX 50000
#define MMAX 800000
#define DEMB 256      // D = H*DK = H*DV = 256
#define HEADS 8
#define DHEAD 32

// ---------------------------------------------------------------------------
// Scratch (device globals: allocation-free per harness rules)
// ---------------------------------------------------------------------------
__device__ float g_K  [(size_t)NMAX * DEMB];
__device__ float g_Q  [(size_t)NMAX * DEMB];
__device__ float g_V  [(size_t)NMAX * DEMB];
__device__ float g_att[(size_t)MMAX * HEADS];   // qk logits, then att in-place
__device__ float g_sums[(size_t)NMAX * HEADS];  // segment softmax denominators
__device__ float g_agg[(size_t)NMAX * DEMB];    // scatter-add accumulator
__device__ float g_h1 [(size_t)NMAX * DEMB];    // after Wagg
__device__ float g_bmax[1024];                  // per-block maxima
__device__ float g_scale[1];                    // 3 / max(qk)

// ---------------------------------------------------------------------------
// cp.async helpers
// ---------------------------------------------------------------------------
__device__ __forceinline__ void cp_async16(void* smem_dst, const void* gsrc, int src_bytes)
{
    uint32_t s = (uint32_t)__cvta_generic_to_shared(smem_dst);
    asm volatile("cp.async.ca.shared.global [%0], [%1], 16, %2;\n"
                 :: "r"(s), "l"(gsrc), "r"(src_bytes));
}
__device__ __forceinline__ void cp_commit() { asm volatile("cp.async.commit_group;\n"); }
template <int N>
__device__ __forceinline__ void cp_wait() { asm volatile("cp.async.wait_group %0;\n" :: "n"(N)); }

// ---------------------------------------------------------------------------
// tf32 tensor-core GEMM: C[n,j] = epi( sum_d actIn(A[n,d]) * W[d,j] + bias[j] )
// BM=128, BN=64, BK=16; 256 threads = 8 warps in 4(m) x 2(n); warp tile 32x32.
// mma.sync.aligned.m16n8k8.row.col.f32.tf32.tf32.f32
// Smem pads: As stride 20 -> frag banks (20r+c) all distinct;
//            Bs stride 72 -> frag banks (8k+n) all distinct.
// ---------------------------------------------------------------------------
#define BM 128
#define BN 64
#define BK 16
#define AS_STRIDE 20
#define BS_STRIDE 72

template <bool RELU_IN, bool RELU_OUT, bool RESID>
__global__ __launch_bounds__(256)
void gemm_tf32_kernel(const float* __restrict__ A, const float* __restrict__ W,
                      const float* __restrict__ bias, const float* __restrict__ resid,
                      float* __restrict__ C, int Nr)
{
    __shared__ float As[2][BM][AS_STRIDE];   // [stage][m][k] (16 of 20 used)
    __shared__ float Bs[2][BK][BS_STRIDE];   // [stage][k][n] (64 of 72 used)

    const int tid  = threadIdx.x;
    const int lane = tid & 31;
    const int wid  = tid >> 5;
    const int wm   = wid & 3;                // m-warp: offset wm*32
    const int wn   = wid >> 2;               // n-warp: offset wn*32
    const int brow = blockIdx.x * BM;
    const int bcol = blockIdx.y * BN;
    const int fr   = lane >> 2;              // fragment "groupID"
    const int fc   = lane & 3;               // fragment "threadID_in_group"

    float acc[2][4][4];
    #pragma unroll
    for (int i = 0; i < 2; i++)
        #pragma unroll
        for (int j = 0; j < 4; j++)
            #pragma unroll
            for (int q = 0; q < 4; q++) acc[i][j][q] = 0.f;

    // A loader: 512 16B-chunks (128 rows x 4), 2 per thread.
    const int ac0_row = tid >> 2;
    const int ac0_kk  = (tid & 3) * 4;
    const int ac1_row = (tid + 256) >> 2;
    const int ac1_kk  = ac0_kk;
    // B loader: 256 chunks (16 rows x 16), 1 per thread.
    const int bw_k = tid >> 4;
    const int bw_n = (tid & 15) * 4;

    // ---- preload tile 0 ----
    {
        const int k0 = 0;
        cp_async16(&As[0][ac0_row][ac0_kk],
                   A + (size_t)(brow + ac0_row) * DEMB + k0 + ac0_kk,
                   (brow + ac0_row < Nr) ? 16 : 0);
        cp_async16(&As[0][ac1_row][ac1_kk],
                   A + (size_t)(brow + ac1_row) * DEMB + k0 + ac1_kk,
                   (brow + ac1_row < Nr) ? 16 : 0);
        cp_async16(&Bs[0][bw_k][bw_n],
                   W + (size_t)(k0 + bw_k) * DEMB + bcol + bw_n, 16);
        cp_commit();
    }

    #pragma unroll 1
    for (int it = 0; it < DEMB / BK; it++) {
        if (it < DEMB / BK - 1) {
            const int k0 = (it + 1) * BK;
            const int st = (it + 1) & 1;
            cp_async16(&As[st][ac0_row][ac0_kk],
                       A + (size_t)(brow + ac0_row) * DEMB + k0 + ac0_kk,
                       (brow + ac0_row < Nr) ? 16 : 0);
            cp_async16(&As[st][ac1_row][ac1_kk],
                       A + (size_t)(brow + ac1_row) * DEMB + k0 + ac1_kk,
                       (brow + ac1_row < Nr) ? 16 : 0);
            cp_async16(&Bs[st][bw_k][bw_n],
                       W + (size_t)(k0 + bw_k) * DEMB + bcol + bw_n, 16);
            cp_commit();
            cp_wait<1>();
        } else {
            cp_wait<0>();
        }
        __syncthreads();

        const int st = it & 1;
        #pragma unroll
        for (int ks = 0; ks < 2; ks++) {
            const int kb = ks * 8;
            // A fragments: 2 m-tiles x 4 regs
            uint32_t afr[2][4];
            #pragma unroll
            for (int mt = 0; mt < 2; mt++) {
                const int rb = wm * 32 + mt * 16 + fr;
                float a0 = As[st][rb    ][kb + fc];
                float a1 = As[st][rb + 8][kb + fc];
                float a2 = As[st][rb    ][kb + fc + 4];
                float a3 = As[st][rb + 8][kb + fc + 4];
                if (RELU_IN) {
                    a0 = fmaxf(a0, 0.f); a1 = fmaxf(a1, 0.f);
                    a2 = fmaxf(a2, 0.f); a3 = fmaxf(a3, 0.f);
                }
                afr[mt][0] = __float_as_uint(a0);
                afr[mt][1] = __float_as_uint(a1);
                afr[mt][2] = __float_as_uint(a2);
                afr[mt][3] = __float_as_uint(a3);
            }
            // B fragments: 4 n-tiles x 2 regs
            uint32_t bfr[4][2];
            #pragma unroll
            for (int nt = 0; nt < 4; nt++) {
                const int nb = wn * 32 + nt * 8 + fr;
                bfr[nt][0] = __float_as_uint(Bs[st][kb + fc    ][nb]);
                bfr[nt][1] = __float_as_uint(Bs[st][kb + fc + 4][nb]);
            }
            #pragma unroll
            for (int mt = 0; mt < 2; mt++)
                #pragma unroll
                for (int nt = 0; nt < 4; nt++) {
                    asm volatile(
                        "mma.sync.aligned.m16n8k8.row.col.f32.tf32.tf32.f32 "
                        "{%0,%1,%2,%3}, {%4,%5,%6,%7}, {%8,%9}, {%0,%1,%2,%3};\n"
                        : "+f"(acc[mt][nt][0]), "+f"(acc[mt][nt][1]),
                          "+f"(acc[mt][nt][2]), "+f"(acc[mt][nt][3])
                        : "r"(afr[mt][0]), "r"(afr[mt][1]),
                          "r"(afr[mt][2]), "r"(afr[mt][3]),
                          "r"(bfr[nt][0]), "r"(bfr[nt][1]));
                }
        }
        __syncthreads();
    }

    // ---- epilogue ----
    #pragma unroll
    for (int mt = 0; mt < 2; mt++) {
        #pragma unroll
        for (int nt = 0; nt < 4; nt++) {
            const int row0 = brow + wm * 32 + mt * 16 + fr;
            const int col0 = bcol + wn * 32 + nt * 8 + 2 * fc;
            const float2 bi = *(const float2*)(bias + col0);
            #pragma unroll
            for (int half = 0; half < 2; half++) {
                const int gr = row0 + half * 8;
                if (gr >= Nr) continue;
                float2 o;
                o.x = acc[mt][nt][half * 2 + 0] + bi.x;
                o.y = acc[mt][nt][half * 2 + 1] + bi.y;
                if (RELU_OUT) { o.x = fmaxf(o.x, 0.f); o.y = fmaxf(o.y, 0.f); }
                if (RESID) {
                    const float2 rr = *(const float2*)(resid + (size_t)gr * DEMB + col0);
                    o.x += rr.x; o.y += rr.y;
                }
                *(float2*)(C + (size_t)gr * DEMB + col0) = o;
            }
        }
    }
}

// ---------------------------------------------------------------------------
// Edge QK dots: 4 lanes per head, 8-element serial dot, 2 shuffles.
// ---------------------------------------------------------------------------
__global__ __launch_bounds__(256)
void edge_qk_kernel(const int* __restrict__ recv, const int* __restrict__ send,
                    const float* __restrict__ Q, const float* __restrict__ K,
                    float* __restrict__ qk, float* __restrict__ bmax, int M)
{
    const int lane   = threadIdx.x & 31;
    const int warp   = (blockIdx.x * blockDim.x + threadIdx.x) >> 5;
    const int nwarps = (gridDim.x * blockDim.x) >> 5;
    const int h   = lane >> 2;
    const int q4  = lane & 3;
    const int off = h * DHEAD + q4 * 8;

    float lmax = -3.402823e38f;
    for (int e = warp; e < M; e += nwarps) {
        const int r = recv[e];
        const int s = send[e];
        const float4* __restrict__ q = (const float4*)(Q + (size_t)r * DEMB + off);
        const float4* __restrict__ k = (const float4*)(K + (size_t)s * DEMB + off);
        const float4 qa = q[0], qb = q[1];
        const float4 ka = k[0], kb = k[1];
        float p = qa.x * ka.x + qa.y * ka.y + qa.z * ka.z + qa.w * ka.w
                + qb.x * kb.x + qb.y * kb.y + qb.z * kb.z + qb.w * kb.w;
        p += __shfl_xor_sync(0xffffffffu, p, 1);
        p += __shfl_xor_sync(0xffffffffu, p, 2);
        lmax = fmaxf(lmax, p);
        if (q4 == 0) qk[(size_t)e * HEADS + h] = p;
    }

    __shared__ float sm[256];
    sm[threadIdx.x] = lmax;
    __syncthreads();
    for (int s2 = 128; s2; s2 >>= 1) {
        if (threadIdx.x < s2)
            sm[threadIdx.x] = fmaxf(sm[threadIdx.x], sm[threadIdx.x + s2]);
        __syncthreads();
    }
    if (threadIdx.x == 0) bmax[blockIdx.x] = sm[0];
}

__global__ __launch_bounds__(1024)
void max_reduce_kernel(const float* __restrict__ bmax, int n, float* __restrict__ scale)
{
    __shared__ float sm[1024];
    float v = -3.402823e38f;
    for (int i = threadIdx.x; i < n; i += blockDim.x) v = fmaxf(v, bmax[i]);
    sm[threadIdx.x] = v;
    __syncthreads();
    for (int s = 512; s; s >>= 1) {
        if (threadIdx.x < s) sm[threadIdx.x] = fmaxf(sm[threadIdx.x], sm[threadIdx.x + s]);
        __syncthreads();
    }
    if (threadIdx.x == 0) scale[0] = 3.0f / sm[0];
}

// ---------------------------------------------------------------------------
// att = exp(qk * scale); segment-sum into sums[recv]
// ---------------------------------------------------------------------------
__global__ __launch_bounds__(256)
void edge_att_kernel(const int* __restrict__ recv, float* __restrict__ att,
                     const float* __restrict__ scale, float* __restrict__ sums, int MH)
{
    const float sc = scale[0];
    for (int i = blockIdx.x * blockDim.x + threadIdx.x; i < MH;
         i += gridDim.x * blockDim.x) {
        const int e = i >> 3;
        const int h = i & 7;
        const float a = expf(att[i] * sc);
        att[i] = a;
        atomicAdd(&sums[(size_t)recv[e] * HEADS + h], a);
    }
}

// ---------------------------------------------------------------------------
// Weighted scatter of V[send] into agg[recv] (one warp per edge)
// ---------------------------------------------------------------------------
__global__ __launch_bounds__(256)
void edge_scatter_kernel(const int* __restrict__ recv, const int* __restrict__ send,
                         const float* __restrict__ att, const float* __restrict__ sums,
                         const float* __restrict__ V, float* __restrict__ agg, int M)
{
    const float inv_sqrt_dk = 0.17677669529663687f;  // 1/sqrt(32)
    const int lane   = threadIdx.x & 31;
    const int warp   = (blockIdx.x * blockDim.x + threadIdx.x) >> 5;
    const int nwarps = (gridDim.x * blockDim.x) >> 5;

    for (int e = warp; e < M; e += nwarps) {
        const int r = recv[e];
        const int s = send[e];
        float w[HEADS];
        #pragma unroll
        for (int h = 0; h < HEADS; h++) {
            w[h] = att[(size_t)e * HEADS + h] /
                   sums[(size_t)r * HEADS + h] * inv_sqrt_dk;
        }
        const float* __restrict__ v = V + (size_t)s * DEMB;
        float* __restrict__ o = agg + (size_t)r * DEMB;
        #pragma unroll
        for (int h = 0; h < HEADS; h++)
            atomicAdd(&o[h * DHEAD + lane], w[h] * v[h * DHEAD + lane]);
    }
}

// ---------------------------------------------------------------------------
// Launch
// ---------------------------------------------------------------------------
extern "C" void kernel_launch(void* const* d_in, const int* in_sizes, int n_in,
                              void* d_out, int out_size)
{
    const float* x    = (const float*)d_in[0];
    const int*   ei   = (const int*)  d_in[1];
    const float* Wk   = (const float*)d_in[2];
    const float* bk   = (const float*)d_in[3];
    const float* Wq   = (const float*)d_in[4];
    const float* bq   = (const float*)d_in[5];
    const float* Wv   = (const float*)d_in[6];
    const float* bv   = (const float*)d_in[7];
    const float* Wagg = (const float*)d_in[8];
    const float* bagg = (const float*)d_in[9];
    const float* Wff  = (const float*)d_in[10];
    const float* bff  = (const float*)d_in[11];

    const int Nn = in_sizes[0] / DEMB;   // 50000
    const int M  = in_sizes[1] / 2;      // 800000
    const int* recv = ei;
    const int* send = ei + M;

    float *gK, *gQ, *gV, *gatt, *gsums, *gagg, *gh1, *gbmax, *gscale;
    cudaGetSymbolAddress((void**)&gK,    g_K);
    cudaGetSymbolAddress((void**)&gQ,    g_Q);
    cudaGetSymbolAddress((void**)&gV,    g_V);
    cudaGetSymbolAddress((void**)&gatt,  g_att);
    cudaGetSymbolAddress((void**)&gsums, g_sums);
    cudaGetSymbolAddress((void**)&gagg,  g_agg);
    cudaGetSymbolAddress((void**)&gh1,   g_h1);
    cudaGetSymbolAddress((void**)&gbmax, g_bmax);
    cudaGetSymbolAddress((void**)&gscale, g_scale);

    // Reset accumulators every launch (graph replays must be deterministic).
    cudaMemsetAsync(gsums, 0, (size_t)Nn * HEADS * sizeof(float), 0);
    cudaMemsetAsync(gagg,  0, (size_t)Nn * DEMB  * sizeof(float), 0);

    const dim3 gg((Nn + BM - 1) / BM, DEMB / BN);   // (391, 4)

    // 1) Projections K, Q, V (tf32 tensor cores)
    gemm_tf32_kernel<false, false, false><<<gg, 256>>>(x, Wk, bk, nullptr, gK, Nn);
    gemm_tf32_kernel<false, false, false><<<gg, 256>>>(x, Wq, bq, nullptr, gQ, Nn);
    gemm_tf32_kernel<false, false, false><<<gg, 256>>>(x, Wv, bv, nullptr, gV, Nn);

    // 2) Edge logits + global max
    edge_qk_kernel<<<1024, 256>>>(recv, send, gQ, gK, gatt, gbmax, M);
    max_reduce_kernel<<<1, 1024>>>(gbmax, 1024, gscale);

    // 3) exp + segment sums
    edge_att_kernel<<<2048, 256>>>(recv, gatt, gscale, gsums, M * HEADS);

    // 4) Weighted scatter into agg
    edge_scatter_kernel<<<2048, 256>>>(recv, send, gatt, gsums, gV, gagg, M);

    // 5) relu(agg) @ Wagg + bagg, relu
    gemm_tf32_kernel<true, true, false><<<gg, 256>>>(gagg, Wagg, bagg, nullptr, gh1, Nn);

    // 6) h1 @ Wff + bff, relu, + x residual -> d_out
    gemm_tf32_kernel<false, true, true><<<gg, 256>>>(gh1, Wff, bff, x, (float*)d_out, Nn);
}

// round 5
// speedup vs baseline: 2.3842x; 1.1309x over previous
#include <cuda_runtime.h>
#include <cuda_bf16.h>
#include <math.h>
#include <stdint.h>

// Problem constants (fixed by the dataset)
#define NMAX 50000
#define MMAX 800000
#define DEMB 256      // D = H*DK = H*DV = 256
#define HEADS 8
#define DHEAD 32

// ---------------------------------------------------------------------------
// Scratch (device globals: allocation-free per harness rules)
// ---------------------------------------------------------------------------
__device__ float g_K  [(size_t)NMAX * DEMB];
__device__ float g_Q  [(size_t)NMAX * DEMB];
__device__ float g_V  [(size_t)NMAX * DEMB];
__device__ float g_qk [(size_t)MMAX * HEADS];   // logits, CSR edge order
__device__ float g_agg[(size_t)NMAX * DEMB];    // attention output
__device__ float g_h1 [(size_t)NMAX * DEMB];    // after Wagg
__device__ float g_bmax[4096];                  // per-block maxima
__device__ float g_scale[1];                    // 3 / max(qk)
__device__ int   g_deg [NMAX];
__device__ int   g_off [NMAX + 1];
__device__ int   g_cur [NMAX];
__device__ int   g_csr_send[MMAX];

// ---------------------------------------------------------------------------
// cp.async helpers
// ---------------------------------------------------------------------------
__device__ __forceinline__ void cp_async16(void* smem_dst, const void* gsrc, int src_bytes)
{
    uint32_t s = (uint32_t)__cvta_generic_to_shared(smem_dst);
    asm volatile("cp.async.ca.shared.global [%0], [%1], 16, %2;\n"
                 :: "r"(s), "l"(gsrc), "r"(src_bytes));
}
__device__ __forceinline__ void cp_commit() { asm volatile("cp.async.commit_group;\n"); }
template <int N>
__device__ __forceinline__ void cp_wait() { asm volatile("cp.async.wait_group %0;\n" :: "n"(N)); }

// ---------------------------------------------------------------------------
// tf32 tensor-core GEMM (unchanged from R3 — known good)
// BM=128, BN=64, BK=16; 256 threads = 8 warps in 4(m) x 2(n); warp tile 32x32.
// ---------------------------------------------------------------------------
#define BM 128
#define BN 64
#define BK 16
#define AS_STRIDE 20
#define BS_STRIDE 72

template <bool RELU_IN, bool RELU_OUT, bool RESID>
__global__ __launch_bounds__(256)
void gemm_tf32_kernel(const float* __restrict__ A, const float* __restrict__ W,
                      const float* __restrict__ bias, const float* __restrict__ resid,
                      float* __restrict__ C, int Nr)
{
    __shared__ float As[2][BM][AS_STRIDE];
    __shared__ float Bs[2][BK][BS_STRIDE];

    const int tid  = threadIdx.x;
    const int lane = tid & 31;
    const int wid  = tid >> 5;
    const int wm   = wid & 3;
    const int wn   = wid >> 2;
    const int brow = blockIdx.x * BM;
    const int bcol = blockIdx.y * BN;
    const int fr   = lane >> 2;
    const int fc   = lane & 3;

    float acc[2][4][4];
    #pragma unroll
    for (int i = 0; i < 2; i++)
        #pragma unroll
        for (int j = 0; j < 4; j++)
            #pragma unroll
            for (int q = 0; q < 4; q++) acc[i][j][q] = 0.f;

    const int ac0_row = tid >> 2;
    const int ac0_kk  = (tid & 3) * 4;
    const int ac1_row = (tid + 256) >> 2;
    const int ac1_kk  = ac0_kk;
    const int bw_k = tid >> 4;
    const int bw_n = (tid & 15) * 4;

    {
        cp_async16(&As[0][ac0_row][ac0_kk],
                   A + (size_t)(brow + ac0_row) * DEMB + ac0_kk,
                   (brow + ac0_row < Nr) ? 16 : 0);
        cp_async16(&As[0][ac1_row][ac1_kk],
                   A + (size_t)(brow + ac1_row) * DEMB + ac1_kk,
                   (brow + ac1_row < Nr) ? 16 : 0);
        cp_async16(&Bs[0][bw_k][bw_n],
                   W + (size_t)bw_k * DEMB + bcol + bw_n, 16);
        cp_commit();
    }

    #pragma unroll 1
    for (int it = 0; it < DEMB / BK; it++) {
        if (it < DEMB / BK - 1) {
            const int k0 = (it + 1) * BK;
            const int st = (it + 1) & 1;
            cp_async16(&As[st][ac0_row][ac0_kk],
                       A + (size_t)(brow + ac0_row) * DEMB + k0 + ac0_kk,
                       (brow + ac0_row < Nr) ? 16 : 0);
            cp_async16(&As[st][ac1_row][ac1_kk],
                       A + (size_t)(brow + ac1_row) * DEMB + k0 + ac1_kk,
                       (brow + ac1_row < Nr) ? 16 : 0);
            cp_async16(&Bs[st][bw_k][bw_n],
                       W + (size_t)(k0 + bw_k) * DEMB + bcol + bw_n, 16);
            cp_commit();
            cp_wait<1>();
        } else {
            cp_wait<0>();
        }
        __syncthreads();

        const int st = it & 1;
        #pragma unroll
        for (int ks = 0; ks < 2; ks++) {
            const int kb = ks * 8;
            uint32_t afr[2][4];
            #pragma unroll
            for (int mt = 0; mt < 2; mt++) {
                const int rb = wm * 32 + mt * 16 + fr;
                float a0 = As[st][rb    ][kb + fc];
                float a1 = As[st][rb + 8][kb + fc];
                float a2 = As[st][rb    ][kb + fc + 4];
                float a3 = As[st][rb + 8][kb + fc + 4];
                if (RELU_IN) {
                    a0 = fmaxf(a0, 0.f); a1 = fmaxf(a1, 0.f);
                    a2 = fmaxf(a2, 0.f); a3 = fmaxf(a3, 0.f);
                }
                afr[mt][0] = __float_as_uint(a0);
                afr[mt][1] = __float_as_uint(a1);
                afr[mt][2] = __float_as_uint(a2);
                afr[mt][3] = __float_as_uint(a3);
            }
            uint32_t bfr[4][2];
            #pragma unroll
            for (int nt = 0; nt < 4; nt++) {
                const int nb = wn * 32 + nt * 8 + fr;
                bfr[nt][0] = __float_as_uint(Bs[st][kb + fc    ][nb]);
                bfr[nt][1] = __float_as_uint(Bs[st][kb + fc + 4][nb]);
            }
            #pragma unroll
            for (int mt = 0; mt < 2; mt++)
                #pragma unroll
                for (int nt = 0; nt < 4; nt++) {
                    asm volatile(
                        "mma.sync.aligned.m16n8k8.row.col.f32.tf32.tf32.f32 "
                        "{%0,%1,%2,%3}, {%4,%5,%6,%7}, {%8,%9}, {%0,%1,%2,%3};\n"
                        : "+f"(acc[mt][nt][0]), "+f"(acc[mt][nt][1]),
                          "+f"(acc[mt][nt][2]), "+f"(acc[mt][nt][3])
                        : "r"(afr[mt][0]), "r"(afr[mt][1]),
                          "r"(afr[mt][2]), "r"(afr[mt][3]),
                          "r"(bfr[nt][0]), "r"(bfr[nt][1]));
                }
        }
        __syncthreads();
    }

    #pragma unroll
    for (int mt = 0; mt < 2; mt++) {
        #pragma unroll
        for (int nt = 0; nt < 4; nt++) {
            const int row0 = brow + wm * 32 + mt * 16 + fr;
            const int col0 = bcol + wn * 32 + nt * 8 + 2 * fc;
            const float2 bi = *(const float2*)(bias + col0);
            #pragma unroll
            for (int half = 0; half < 2; half++) {
                const int gr = row0 + half * 8;
                if (gr >= Nr) continue;
                float2 o;
                o.x = acc[mt][nt][half * 2 + 0] + bi.x;
                o.y = acc[mt][nt][half * 2 + 1] + bi.y;
                if (RELU_OUT) { o.x = fmaxf(o.x, 0.f); o.y = fmaxf(o.y, 0.f); }
                if (RESID) {
                    const float2 rr = *(const float2*)(resid + (size_t)gr * DEMB + col0);
                    o.x += rr.x; o.y += rr.y;
                }
                *(float2*)(C + (size_t)gr * DEMB + col0) = o;
            }
        }
    }
}

// ---------------------------------------------------------------------------
// CSR build: histogram -> scan -> scatter
// ---------------------------------------------------------------------------
__global__ __launch_bounds__(256)
void hist_kernel(const int* __restrict__ recv, int* __restrict__ deg, int M)
{
    const int e = blockIdx.x * 256 + threadIdx.x;
    if (e < M) atomicAdd(&deg[recv[e]], 1);
}

__global__ __launch_bounds__(1024)
void scan_kernel(const int* __restrict__ deg, int N,
                 int* __restrict__ off, int* __restrict__ cur)
{
    __shared__ int part[1024];
    const int tid = threadIdx.x;
    const int chunk = (N + 1023) / 1024;
    const int start = min(tid * chunk, N);
    const int end   = min(start + chunk, N);

    int s = 0;
    for (int i = start; i < end; i++) s += deg[i];
    part[tid] = s;
    __syncthreads();

    // Hillis-Steele inclusive scan
    for (int d = 1; d < 1024; d <<= 1) {
        int v = part[tid];
        int a = (tid >= d) ? part[tid - d] : 0;
        __syncthreads();
        part[tid] = v + a;
        __syncthreads();
    }
    int run = (tid == 0) ? 0 : part[tid - 1];
    for (int i = start; i < end; i++) {
        off[i] = run;
        cur[i] = run;
        run += deg[i];
    }
    if (end == N) off[N] = part[1023];
}

__global__ __launch_bounds__(256)
void csr_scatter_kernel(const int* __restrict__ recv, const int* __restrict__ send,
                        int* __restrict__ cur, int* __restrict__ csr_send, int M)
{
    const int e = blockIdx.x * 256 + threadIdx.x;
    if (e < M) {
        const int pos = atomicAdd(&cur[recv[e]], 1);
        csr_send[pos] = send[e];
    }
}

// ---------------------------------------------------------------------------
// Pass 1: per-node QK logits (Q loaded once per node; only K gathered) + max
// ---------------------------------------------------------------------------
__global__ __launch_bounds__(256)
void pass1_qk_kernel(const int* __restrict__ off, const int* __restrict__ csr_send,
                     const float* __restrict__ Q, const float* __restrict__ K,
                     float* __restrict__ qk, float* __restrict__ bmax, int N)
{
    const int lane = threadIdx.x & 31;
    const int warp = blockIdx.x * 8 + (threadIdx.x >> 5);
    const int nw   = gridDim.x * 8;
    const int h    = lane >> 2;
    const int offl = h * DHEAD + (lane & 3) * 8;

    float lmax = -3.402823e38f;
    for (int n = warp; n < N; n += nw) {
        const int o0 = off[n], o1 = off[n + 1];
        if (o0 == o1) continue;
        const float4* __restrict__ q = (const float4*)(Q + (size_t)n * DEMB + offl);
        const float4 qa = q[0], qb = q[1];
        for (int i = o0; i < o1; i++) {
            const int s = csr_send[i];
            const float4* __restrict__ k = (const float4*)(K + (size_t)s * DEMB + offl);
            const float4 ka = k[0], kb = k[1];
            float p = qa.x * ka.x + qa.y * ka.y + qa.z * ka.z + qa.w * ka.w
                    + qb.x * kb.x + qb.y * kb.y + qb.z * kb.z + qb.w * kb.w;
            p += __shfl_xor_sync(0xffffffffu, p, 1);
            p += __shfl_xor_sync(0xffffffffu, p, 2);
            lmax = fmaxf(lmax, p);
            if ((lane & 3) == 0) qk[(size_t)i * HEADS + h] = p;
        }
    }

    __shared__ float sm[256];
    sm[threadIdx.x] = lmax;
    __syncthreads();
    for (int s2 = 128; s2; s2 >>= 1) {
        if (threadIdx.x < s2)
            sm[threadIdx.x] = fmaxf(sm[threadIdx.x], sm[threadIdx.x + s2]);
        __syncthreads();
    }
    if (threadIdx.x == 0) bmax[blockIdx.x] = sm[0];
}

__global__ __launch_bounds__(1024)
void max_reduce_kernel(const float* __restrict__ bmax, int n, float* __restrict__ scale)
{
    __shared__ float sm[1024];
    float v = -3.402823e38f;
    for (int i = threadIdx.x; i < n; i += blockDim.x) v = fmaxf(v, bmax[i]);
    sm[threadIdx.x] = v;
    __syncthreads();
    for (int s = 512; s; s >>= 1) {
        if (threadIdx.x < s) sm[threadIdx.x] = fmaxf(sm[threadIdx.x], sm[threadIdx.x + s]);
        __syncthreads();
    }
    if (threadIdx.x == 0) scale[0] = 3.0f / sm[0];
}

// ---------------------------------------------------------------------------
// Pass 2: per-node softmax sums in registers + weighted V gather, no atomics.
// exp recomputed from logits with the same expf both times -> exact normalization.
// ---------------------------------------------------------------------------
__global__ __launch_bounds__(256)
void pass2_agg_kernel(const int* __restrict__ off, const int* __restrict__ csr_send,
                      const float* __restrict__ qk, const float* __restrict__ scale,
                      const float* __restrict__ V, float* __restrict__ agg, int N)
{
    const float isq = 0.17677669529663687f;  // 1/sqrt(32)
    const float sc  = scale[0];
    const int lane = threadIdx.x & 31;
    const int warp = blockIdx.x * 8 + (threadIdx.x >> 5);
    const int nw   = gridDim.x * 8;
    const int h    = lane >> 2;
    const int offl = h * DHEAD + (lane & 3) * 8;

    for (int n = warp; n < N; n += nw) {
        const int o0 = off[n], o1 = off[n + 1];

        // softmax denominators: lane l accumulates head (l & 7)
        float sp = 0.f;
        for (int idx = o0 * HEADS + lane; idx < o1 * HEADS; idx += 32)
            sp += expf(qk[idx] * sc);
        sp += __shfl_xor_sync(0xffffffffu, sp, 8);
        sp += __shfl_xor_sync(0xffffffffu, sp, 16);
        const float sumh = __shfl_sync(0xffffffffu, sp, h);  // lanes 0..7 hold heads 0..7
        const float winv = isq / sumh;

        float a0 = 0.f, a1 = 0.f, a2 = 0.f, a3 = 0.f;
        float a4 = 0.f, a5 = 0.f, a6 = 0.f, a7 = 0.f;
        for (int i = o0; i < o1; i++) {
            const int s = csr_send[i];
            const float w = expf(qk[(size_t)i * HEADS + h] * sc) * winv;
            const float4* __restrict__ v = (const float4*)(V + (size_t)s * DEMB + offl);
            const float4 va = v[0], vb = v[1];
            a0 += w * va.x; a1 += w * va.y; a2 += w * va.z; a3 += w * va.w;
            a4 += w * vb.x; a5 += w * vb.y; a6 += w * vb.z; a7 += w * vb.w;
        }
        float4* __restrict__ o = (float4*)(agg + (size_t)n * DEMB + offl);
        o[0] = make_float4(a0, a1, a2, a3);
        o[1] = make_float4(a4, a5, a6, a7);
    }
}

// ---------------------------------------------------------------------------
// Launch
// ---------------------------------------------------------------------------
extern "C" void kernel_launch(void* const* d_in, const int* in_sizes, int n_in,
                              void* d_out, int out_size)
{
    const float* x    = (const float*)d_in[0];
    const int*   ei   = (const int*)  d_in[1];
    const float* Wk   = (const float*)d_in[2];
    const float* bk   = (const float*)d_in[3];
    const float* Wq   = (const float*)d_in[4];
    const float* bq   = (const float*)d_in[5];
    const float* Wv   = (const float*)d_in[6];
    const float* bv   = (const float*)d_in[7];
    const float* Wagg = (const float*)d_in[8];
    const float* bagg = (const float*)d_in[9];
    const float* Wff  = (const float*)d_in[10];
    const float* bff  = (const float*)d_in[11];

    const int Nn = in_sizes[0] / DEMB;   // 50000
    const int M  = in_sizes[1] / 2;      // 800000
    const int* recv = ei;
    const int* send = ei + M;

    float *gK, *gQ, *gV, *gqk, *gagg, *gh1, *gbmax, *gscale;
    int *gdeg, *goff, *gcur, *gcsr;
    cudaGetSymbolAddress((void**)&gK,    g_K);
    cudaGetSymbolAddress((void**)&gQ,    g_Q);
    cudaGetSymbolAddress((void**)&gV,    g_V);
    cudaGetSymbolAddress((void**)&gqk,   g_qk);
    cudaGetSymbolAddress((void**)&gagg,  g_agg);
    cudaGetSymbolAddress((void**)&gh1,   g_h1);
    cudaGetSymbolAddress((void**)&gbmax, g_bmax);
    cudaGetSymbolAddress((void**)&gscale, g_scale);
    cudaGetSymbolAddress((void**)&gdeg,  g_deg);
    cudaGetSymbolAddress((void**)&goff,  g_off);
    cudaGetSymbolAddress((void**)&gcur,  g_cur);
    cudaGetSymbolAddress((void**)&gcsr,  g_csr_send);

    const int eg = (M + 255) / 256;      // edge-parallel grid
    const dim3 gg((Nn + BM - 1) / BM, DEMB / BN);   // (391, 4)

    // CSR build (overlappable with projections in issue order)
    cudaMemsetAsync(gdeg, 0, (size_t)Nn * sizeof(int), 0);
    hist_kernel<<<eg, 256>>>(recv, gdeg, M);
    scan_kernel<<<1, 1024>>>(gdeg, Nn, goff, gcur);
    csr_scatter_kernel<<<eg, 256>>>(recv, send, gcur, gcsr, M);

    // Projections K, Q, V (tf32 tensor cores)
    gemm_tf32_kernel<false, false, false><<<gg, 256>>>(x, Wk, bk, nullptr, gK, Nn);
    gemm_tf32_kernel<false, false, false><<<gg, 256>>>(x, Wq, bq, nullptr, gQ, Nn);
    gemm_tf32_kernel<false, false, false><<<gg, 256>>>(x, Wv, bv, nullptr, gV, Nn);

    // Pass 1: logits + global max
    pass1_qk_kernel<<<2048, 256>>>(goff, gcsr, gQ, gK, gqk, gbmax, Nn);
    max_reduce_kernel<<<1, 1024>>>(gbmax, 2048, gscale);

    // Pass 2: softmax + weighted aggregation (atomic-free)
    pass2_agg_kernel<<<2048, 256>>>(goff, gcsr, gqk, gscale, gV, gagg, Nn);

    // Epilogue GEMMs
    gemm_tf32_kernel<true, true, false><<<gg, 256>>>(gagg, Wagg, bagg, nullptr, gh1, Nn);
    gemm_tf32_kernel<false, true, true><<<gg, 256>>>(gh1, Wff, bff, x, (float*)d_out, Nn);
}